// round 9
// baseline (speedup 1.0000x reference)
#include <cuda_runtime.h>
#include <cuda_fp16.h>
#include <cstdint>

// VectorQuantizer via mma.sync m16n8k16 (fp16 in / fp32 acc), fp16 hi/lo split
// (3 passes). 32 rows per warp (2 A-fragment sets) -> 6 HMMA per B-LDSM.
// MTILE=512, grid=128 CTAs = exactly one wave on 148 SMs.
// Scores init to ||w||^2+||x||^2+1 (>=~1, u32-comparable); tournament top-2;
// exact fp32 rerank of the two candidates.

#define D      64
#define K      1024
#define MTILE  512        // points per CTA (16 warps x 32 rows)
#define WTILE  128        // codewords per tile
#define KT     (K / WTILE)
#define BLOCK  512
#define HW     1024       // d-stride inside x

// ---- smem layout (bytes) ----
#define OFF_YHI 0                 // 512 x 128B fp16
#define OFF_YLO 65536
#define OFF_W   131072            // 2 bufs x (hi 16KB + lo 16KB)
#define W_BUF   32768
#define OFF_WN  196608            // 1024 fp32 norms
#define OFF_XN  200704            // 512 fp32 ||x||^2
#define OFF_TOP 202752            // 512 x uint2
#define OFF_IDX 206848            // 512 int
#define SMEM_TOTAL 208896

#define SW(o) ((o) ^ (((o) >> 3) & 0x70))

// ---- global scratch: swizzled fp16 codebook tiles (hi,lo) + norms ----
__device__ __align__(1024) static char  g_wsw[KT][2][WTILE * 128];
__device__ __align__(16)   static float g_wn[K];

static __device__ __forceinline__ uint32_t smem_u32(const void* p) {
    uint32_t a;
    asm("{ .reg .u64 t; cvta.to.shared.u64 t, %1; cvt.u32.u64 %0, t; }" : "=r"(a) : "l"(p));
    return a;
}
static __device__ __forceinline__ void cp16(uint32_t saddr, const void* g) {
    asm volatile("cp.async.cg.shared.global [%0], [%1], 16;"
                 :: "r"(saddr), "l"((size_t)__cvta_generic_to_global(g)) : "memory");
}
static __device__ __forceinline__ void ldsm4(uint32_t r[4], uint32_t addr) {
    asm volatile("ldmatrix.sync.aligned.m8n8.x4.shared.b16 {%0,%1,%2,%3}, [%4];"
                 : "=r"(r[0]), "=r"(r[1]), "=r"(r[2]), "=r"(r[3]) : "r"(addr));
}
static __device__ __forceinline__ void mma16816(float c[4], const uint32_t a[4],
                                                uint32_t b0, uint32_t b1) {
    asm volatile("mma.sync.aligned.m16n8k16.row.col.f32.f16.f16.f32 "
                 "{%0,%1,%2,%3}, {%4,%5,%6,%7}, {%8,%9}, {%0,%1,%2,%3};"
                 : "+f"(c[0]), "+f"(c[1]), "+f"(c[2]), "+f"(c[3])
                 : "r"(a[0]), "r"(a[1]), "r"(a[2]), "r"(a[3]), "r"(b0), "r"(b1));
}
static __device__ __forceinline__ uint32_t umn(uint32_t a, uint32_t b) { return a < b ? a : b; }
static __device__ __forceinline__ uint32_t umx(uint32_t a, uint32_t b) { return a > b ? a : b; }

// scores >= ~1 -> raw float bits order as u32. 13 mantissa bits + 10 index bits.
static __device__ __forceinline__ uint32_t fkey(float v, int col) {
    return (__float_as_uint(v) & 0xFFFFFC00u) | (uint32_t)col;
}
// top-2 of 4 keys, merged into running (k1,k2)
static __device__ __forceinline__ void top2of4_acc(uint32_t& k1, uint32_t& k2,
                                                   uint32_t a, uint32_t b,
                                                   uint32_t c, uint32_t d) {
    uint32_t p1 = umn(a, b), p2 = umx(a, b);
    uint32_t q1 = umn(c, d), q2 = umx(c, d);
    uint32_t t1 = umn(p1, q1);
    uint32_t t2 = umn(umx(p1, q1), umn(p2, q2));
    uint32_t n1 = umn(k1, t1);
    k2 = umn(umx(k1, t1), umn(k2, t2));
    k1 = n1;
}

// ---------------- pre-kernel: convert codebook once ----------------
__global__ __launch_bounds__(256)
void vq_prep_kernel(const float* __restrict__ w)
{
    const int gid = blockIdx.x * 256 + threadIdx.x;   // 128 blocks -> 32768 threads
    {
        const int i  = gid;                           // pair index
        const int kr = i >> 5;                        // codeword 0..1023
        const int p  = i & 31;                        // pair within row
        float2 v = ((const float2*)w)[i];
        __half h0 = __float2half_rn(v.x), h1 = __float2half_rn(v.y);
        __half l0 = __float2half_rn(v.x - __half2float(h0));
        __half l1 = __float2half_rn(v.y - __half2float(h1));
        const int kt = kr >> 7, pr = kr & 127;
        uint32_t o = SW((uint32_t)(pr * 128 + p * 4));
        *(__half2*)(g_wsw[kt][0] + o) = __halves2half2(h0, h1);
        *(__half2*)(g_wsw[kt][1] + o) = __halves2half2(l0, l1);
    }
    if (gid < K) {
        const float4* wr = (const float4*)(w + (size_t)gid * D);
        float s = 0.0f;
#pragma unroll
        for (int q = 0; q < D / 4; q++) {
            float4 f = wr[q];
            s = fmaf(f.x, f.x, s); s = fmaf(f.y, f.y, s);
            s = fmaf(f.z, f.z, s); s = fmaf(f.w, f.w, s);
        }
        g_wn[gid] = s;
    }
}

// ---------------- main kernel ----------------
__global__ __launch_bounds__(BLOCK, 1)
void vq_hmma_kernel(const float* __restrict__ x,
                    const float* __restrict__ w,
                    float* __restrict__ out)
{
    extern __shared__ char sm[];
    const uint32_t smb = smem_u32(sm);
    const int tid  = threadIdx.x;
    const int lane = tid & 31;
    const int warp = tid >> 5;

    const int n0   = blockIdx.x * MTILE;
    const int bimg = n0 >> 10;
    const int hw0  = n0 & (HW - 1);

    // ---- prefetch: norms + tiles 0 and 1 (32KB each = 4 cp16/thread) ----
    if (tid < 256) cp16(smb + OFF_WN + tid * 16, g_wn + tid * 4);
#pragma unroll
    for (int i = 0; i < 4; i++) {
        int off = (tid + i * BLOCK) * 16;
        cp16(smb + OFF_W + off, g_wsw[0][0] + off);
    }
    asm volatile("cp.async.commit_group;" ::: "memory");
#pragma unroll
    for (int i = 0; i < 4; i++) {
        int off = (tid + i * BLOCK) * 16;
        cp16(smb + OFF_W + W_BUF + off, g_wsw[1][0] + off);
    }
    asm volatile("cp.async.commit_group;" ::: "memory");

    // ---- build Y = -2x (fp16 hi/lo, swizzled) + ||x||^2, one point/thread ----
    {
        const float* xp = x + (size_t)bimg * D * HW + hw0 + tid;
        char* yhi = sm + OFF_YHI;
        char* ylo = sm + OFF_YLO;
        const uint32_t rb = (uint32_t)tid * 128;
        float xs = 0.0f;
#pragma unroll
        for (int d = 0; d < D; d += 2) {
            float xv0 = xp[(size_t)d * HW];
            float xv1 = xp[(size_t)(d + 1) * HW];
            xs = fmaf(xv0, xv0, xs);
            xs = fmaf(xv1, xv1, xs);
            float v0 = -2.0f * xv0, v1 = -2.0f * xv1;
            __half h0 = __float2half_rn(v0), h1 = __float2half_rn(v1);
            __half l0 = __float2half_rn(v0 - __half2float(h0));
            __half l1 = __float2half_rn(v1 - __half2float(h1));
            uint32_t o = SW(rb + (uint32_t)d * 2);
            *(__half2*)(yhi + o) = __halves2half2(h0, h1);
            *(__half2*)(ylo + o) = __halves2half2(l0, l1);
        }
        ((float*)(sm + OFF_XN))[tid] = xs + 1.0f;   // +1: scores >= ~1
    }
    __syncthreads();

    // ---- per-lane row offsets: this lane owns 4 rows (2 mtiles x 2 halves) ----
    float xn[2][2];
    {
        const float* xnp = (const float*)(sm + OFF_XN);
        const int r0 = warp * 32 + (lane >> 2);
        xn[0][0] = xnp[r0];      xn[0][1] = xnp[r0 + 8];
        xn[1][0] = xnp[r0 + 16]; xn[1][1] = xnp[r0 + 24];
    }

    // ---- A fragments: 2 m16 tiles x 4 k-chunks x {hi,lo} ----
    uint32_t ahi[2][4][4], alo[2][4][4];
    const int lr = lane & 7;
    const int mI = lane >> 3;
#pragma unroll
    for (int m = 0; m < 2; m++) {
        const uint32_t arow = (uint32_t)(warp * 32 + m * 16 + (mI & 1) * 8 + lr) * 128;
#pragma unroll
        for (int kc = 0; kc < 4; kc++) {
            uint32_t ch = (uint32_t)((kc * 2 + (mI >> 1)) ^ lr) * 16;
            ldsm4(ahi[m][kc], smb + OFF_YHI + arow + ch);
            ldsm4(alo[m][kc], smb + OFF_YLO + arow + ch);
        }
    }

    const uint32_t offb0 = (uint32_t)lr * 128 + (uint32_t)(mI ^ lr) * 16;       // k-chunks 0-3
    const uint32_t offb1 = (uint32_t)lr * 128 + (uint32_t)((4 + mI) ^ lr) * 16; // k-chunks 4-7
    const float* wn = (const float*)(sm + OFF_WN);

    uint32_t tk1[2][2], tk2[2][2];
#pragma unroll
    for (int m = 0; m < 2; m++)
#pragma unroll
        for (int u = 0; u < 2; u++) { tk1[m][u] = 0xFFFFFFFFu; tk2[m][u] = 0xFFFFFFFFu; }

#pragma unroll 1
    for (int kt = 0; kt < KT; kt++) {
        const int buf = kt & 1;
        if (kt < KT - 1) asm volatile("cp.async.wait_group 1;" ::: "memory");
        else             asm volatile("cp.async.wait_group 0;" ::: "memory");
        __syncthreads();

        const uint32_t gbhi = smb + OFF_W + (uint32_t)buf * W_BUF;
        const uint32_t gblo = gbhi + 16384;

#pragma unroll 1
        for (int g = 0; g < WTILE / 16; g++) {           // 16 codewords per group
            const uint32_t th = gbhi + (uint32_t)g * 2048;
            const uint32_t tl = gblo + (uint32_t)g * 2048;
            const int colb = kt * WTILE + g * 16 + 2 * (lane & 3);

            float c[2][2][4];
#pragma unroll
            for (int nt = 0; nt < 2; nt++) {
                float2 nn = *(const float2*)(wn + colb + nt * 8);
#pragma unroll
                for (int m = 0; m < 2; m++) {
                    c[m][nt][0] = nn.x + xn[m][0]; c[m][nt][1] = nn.y + xn[m][0];
                    c[m][nt][2] = nn.x + xn[m][1]; c[m][nt][3] = nn.y + xn[m][1];
                }
            }

            // pass group 1: B = hi, A in {hi, lo}  (8 HMMA per LDSM)
#pragma unroll
            for (int kc32 = 0; kc32 < 2; kc32++) {
                const uint32_t ob = kc32 ? offb1 : offb0;
#pragma unroll
                for (int nt = 0; nt < 2; nt++) {
                    uint32_t bb[4];
                    ldsm4(bb, th + (uint32_t)nt * 1024 + ob);
#pragma unroll
                    for (int m = 0; m < 2; m++) {
                        mma16816(c[m][nt], ahi[m][kc32 * 2],     bb[0], bb[1]);
                        mma16816(c[m][nt], ahi[m][kc32 * 2 + 1], bb[2], bb[3]);
                        mma16816(c[m][nt], alo[m][kc32 * 2],     bb[0], bb[1]);
                        mma16816(c[m][nt], alo[m][kc32 * 2 + 1], bb[2], bb[3]);
                    }
                }
            }
            // pass group 2: B = lo, A = hi  (4 HMMA per LDSM)
#pragma unroll
            for (int kc32 = 0; kc32 < 2; kc32++) {
                const uint32_t ob = kc32 ? offb1 : offb0;
#pragma unroll
                for (int nt = 0; nt < 2; nt++) {
                    uint32_t bb[4];
                    ldsm4(bb, tl + (uint32_t)nt * 1024 + ob);
#pragma unroll
                    for (int m = 0; m < 2; m++) {
                        mma16816(c[m][nt], ahi[m][kc32 * 2],     bb[0], bb[1]);
                        mma16816(c[m][nt], ahi[m][kc32 * 2 + 1], bb[2], bb[3]);
                    }
                }
            }

            // ---- tournament top-2 per owned row ----
#pragma unroll
            for (int m = 0; m < 2; m++) {
                top2of4_acc(tk1[m][0], tk2[m][0],
                            fkey(c[m][0][0], colb),     fkey(c[m][0][1], colb + 1),
                            fkey(c[m][1][0], colb + 8), fkey(c[m][1][1], colb + 9));
                top2of4_acc(tk1[m][1], tk2[m][1],
                            fkey(c[m][0][2], colb),     fkey(c[m][0][3], colb + 1),
                            fkey(c[m][1][2], colb + 8), fkey(c[m][1][3], colb + 9));
            }
        }
        __syncthreads();
        if (kt + 2 < KT) {
            uint32_t dst = smb + OFF_W + (uint32_t)buf * W_BUF;
            const char* src = g_wsw[kt + 2][0];
#pragma unroll
            for (int i = 0; i < 4; i++) {
                int off = (tid + i * BLOCK) * 16;
                cp16(dst + off, src + off);
            }
            asm volatile("cp.async.commit_group;" ::: "memory");
        }
    }

    // ---- merge top-2 across the 4 lanes sharing each row ----
#pragma unroll
    for (int mm = 1; mm <= 2; mm <<= 1) {
#pragma unroll
        for (int m = 0; m < 2; m++)
#pragma unroll
            for (int u = 0; u < 2; u++) {
                uint32_t o1 = __shfl_xor_sync(0xFFFFFFFFu, tk1[m][u], mm);
                uint32_t o2 = __shfl_xor_sync(0xFFFFFFFFu, tk2[m][u], mm);
                uint32_t n1 = umn(tk1[m][u], o1);
                tk2[m][u] = umn(umn(tk2[m][u], o2), umx(tk1[m][u], o1));
                tk1[m][u] = n1;
            }
    }
    if ((lane & 3) == 0) {
        uint2* top = (uint2*)(sm + OFF_TOP);
        const int rb = warp * 32 + (lane >> 2);
#pragma unroll
        for (int m = 0; m < 2; m++)
#pragma unroll
            for (int u = 0; u < 2; u++)
                top[rb + m * 16 + u * 8] = make_uint2(tk1[m][u], tk2[m][u]);
    }
    __syncthreads();

    // ---- exact fp32 rerank of the two candidates (always) ----
    int* sidx = (int*)(sm + OFF_IDX);
    {
        uint2 t = ((const uint2*)(sm + OFF_TOP))[tid];
        int i1 = (int)(t.x & 1023u), i2 = (int)(t.y & 1023u);
        int fi = i1;
        if (i2 != i1) {
            const float* xr = x + (size_t)bimg * D * HW + hw0 + tid;
            const float* w1 = w + (size_t)i1 * D;
            const float* w2 = w + (size_t)i2 * D;
            float s1 = 0.0f, s2 = 0.0f;
#pragma unroll 8
            for (int d = 0; d < D; d++) {
                float xv = xr[(size_t)d * HW];
                float a = w1[d], cc = w2[d];
                s1 = fmaf(a,  fmaf(-2.0f, xv, a),  s1);
                s2 = fmaf(cc, fmaf(-2.0f, xv, cc), s2);
            }
            if (s2 < s1 || (s2 == s1 && i2 < i1)) fi = i2;
        }
        sidx[tid] = fi;
    }
    __syncthreads();

    // ---- coalesced gather of winning codewords ----
    {
        const float4* w4 = (const float4*)w;
        float4* o4 = (float4*)out;
        const size_t obase = (size_t)blockIdx.x * MTILE * (D / 4);
#pragma unroll 4
        for (int i = tid; i < MTILE * (D / 4); i += BLOCK) {
            const int p = i >> 4, d4 = i & 15;
            o4[obase + i] = w4[(size_t)sidx[p] * (D / 4) + d4];
        }
    }
}

extern "C" void kernel_launch(void* const* d_in, const int* in_sizes, int n_in,
                              void* d_out, int out_size)
{
    const float* x = (const float*)d_in[0];   // [64, 64, 32, 32]
    const float* w = (const float*)d_in[1];   // [1024, 64]
    float* out = (float*)d_out;               // [65536, 64]
    (void)in_sizes; (void)n_in; (void)out_size;

    vq_prep_kernel<<<128, 256>>>(w);
    cudaFuncSetAttribute(vq_hmma_kernel, cudaFuncAttributeMaxDynamicSharedMemorySize, SMEM_TOTAL);
    vq_hmma_kernel<<<65536 / MTILE, BLOCK, SMEM_TOTAL>>>(x, w, out);
}

// round 10
// speedup vs baseline: 1.1215x; 1.1215x over previous
#include <cuda_runtime.h>
#include <cuda_fp16.h>
#include <cstdint>

// VectorQuantizer via mma.sync m16n8k16 (fp16 in / fp32 acc), fp16 hi/lo split
// (3 passes). R5 structure with 2 CTAs/SM: MTILE=128, BLOCK=256, smem 102.5KB.
// Scores init to ||w||^2+||x||^2+1 (>=~1, u32-comparable); tournament top-2;
// exact fp32 rerank of the two candidates.

#define D      64
#define K      1024
#define MTILE  128        // points per CTA (8 warps x 16 rows)
#define WTILE  128        // codewords per tile
#define KT     (K / WTILE)
#define BLOCK  256
#define HW     1024       // d-stride inside x

// ---- smem layout (bytes) ----
#define OFF_YHI 0                 // 128 x 128B fp16
#define OFF_YLO 16384
#define OFF_W   32768             // 2 bufs x (hi 16KB + lo 16KB)
#define W_BUF   32768
#define OFF_WN  98304             // 1024 fp32 norms
#define OFF_XN  102400            // 2 x 128 fp32 partial ||x||^2
#define OFF_TOP 103424            // 128 x uint2
#define OFF_IDX 104448            // 128 int
#define SMEM_TOTAL 104960

#define SW(o) ((o) ^ (((o) >> 3) & 0x70))

// ---- global scratch: swizzled fp16 codebook tiles (hi,lo) + norms ----
__device__ __align__(1024) static char  g_wsw[KT][2][WTILE * 128];
__device__ __align__(16)   static float g_wn[K];

static __device__ __forceinline__ uint32_t smem_u32(const void* p) {
    uint32_t a;
    asm("{ .reg .u64 t; cvta.to.shared.u64 t, %1; cvt.u32.u64 %0, t; }" : "=r"(a) : "l"(p));
    return a;
}
static __device__ __forceinline__ void cp16(uint32_t saddr, const void* g) {
    asm volatile("cp.async.cg.shared.global [%0], [%1], 16;"
                 :: "r"(saddr), "l"((size_t)__cvta_generic_to_global(g)) : "memory");
}
static __device__ __forceinline__ void ldsm4(uint32_t r[4], uint32_t addr) {
    asm volatile("ldmatrix.sync.aligned.m8n8.x4.shared.b16 {%0,%1,%2,%3}, [%4];"
                 : "=r"(r[0]), "=r"(r[1]), "=r"(r[2]), "=r"(r[3]) : "r"(addr));
}
static __device__ __forceinline__ void mma16816(float c[4], const uint32_t a[4],
                                                uint32_t b0, uint32_t b1) {
    asm volatile("mma.sync.aligned.m16n8k16.row.col.f32.f16.f16.f32 "
                 "{%0,%1,%2,%3}, {%4,%5,%6,%7}, {%8,%9}, {%0,%1,%2,%3};"
                 : "+f"(c[0]), "+f"(c[1]), "+f"(c[2]), "+f"(c[3])
                 : "r"(a[0]), "r"(a[1]), "r"(a[2]), "r"(a[3]), "r"(b0), "r"(b1));
}
static __device__ __forceinline__ uint32_t umn(uint32_t a, uint32_t b) { return a < b ? a : b; }
static __device__ __forceinline__ uint32_t umx(uint32_t a, uint32_t b) { return a > b ? a : b; }

// scores >= ~1 -> raw float bits order as u32. 13 mantissa bits + 10 index bits.
static __device__ __forceinline__ uint32_t fkey(float v, int col) {
    return (__float_as_uint(v) & 0xFFFFFC00u) | (uint32_t)col;
}
// merge two sorted pairs -> top-2 of union
static __device__ __forceinline__ void mrg2(uint32_t& o1, uint32_t& o2,
                                            uint32_t a1, uint32_t a2,
                                            uint32_t b1, uint32_t b2) {
    o1 = umn(a1, b1);
    o2 = umn(umx(a1, b1), umn(a2, b2));
}
// tournament top-2 of 8 keys (tree depth ~5)
static __device__ __forceinline__ void top2of8(const uint32_t k[8],
                                               uint32_t& t1, uint32_t& t2) {
    uint32_t a1 = umn(k[0], k[1]), a2 = umx(k[0], k[1]);
    uint32_t b1 = umn(k[2], k[3]), b2 = umx(k[2], k[3]);
    uint32_t c1 = umn(k[4], k[5]), c2 = umx(k[4], k[5]);
    uint32_t d1 = umn(k[6], k[7]), d2 = umx(k[6], k[7]);
    uint32_t e1, e2, f1, f2;
    mrg2(e1, e2, a1, a2, b1, b2);
    mrg2(f1, f2, c1, c2, d1, d2);
    mrg2(t1, t2, e1, e2, f1, f2);
}

// ---------------- pre-kernel: convert codebook once ----------------
__global__ __launch_bounds__(256)
void vq_prep_kernel(const float* __restrict__ w)
{
    const int gid = blockIdx.x * 256 + threadIdx.x;   // 128 blocks -> 32768 threads
    {
        const int i  = gid;                           // pair index
        const int kr = i >> 5;                        // codeword 0..1023
        const int p  = i & 31;                        // pair within row
        float2 v = ((const float2*)w)[i];
        __half h0 = __float2half_rn(v.x), h1 = __float2half_rn(v.y);
        __half l0 = __float2half_rn(v.x - __half2float(h0));
        __half l1 = __float2half_rn(v.y - __half2float(h1));
        const int kt = kr >> 7, pr = kr & 127;
        uint32_t o = SW((uint32_t)(pr * 128 + p * 4));
        *(__half2*)(g_wsw[kt][0] + o) = __halves2half2(h0, h1);
        *(__half2*)(g_wsw[kt][1] + o) = __halves2half2(l0, l1);
    }
    if (gid < K) {
        const float4* wr = (const float4*)(w + (size_t)gid * D);
        float s = 0.0f;
#pragma unroll
        for (int q = 0; q < D / 4; q++) {
            float4 f = wr[q];
            s = fmaf(f.x, f.x, s); s = fmaf(f.y, f.y, s);
            s = fmaf(f.z, f.z, s); s = fmaf(f.w, f.w, s);
        }
        g_wn[gid] = s;
    }
}

// ---------------- main kernel ----------------
__global__ __launch_bounds__(BLOCK, 2)
void vq_hmma_kernel(const float* __restrict__ x,
                    const float* __restrict__ w,
                    float* __restrict__ out)
{
    extern __shared__ char sm[];
    const uint32_t smb = smem_u32(sm);
    const int tid  = threadIdx.x;
    const int lane = tid & 31;
    const int warp = tid >> 5;

    const int n0   = blockIdx.x * MTILE;
    const int bimg = n0 >> 10;
    const int hw0  = n0 & (HW - 1);

    // ---- prefetch: norms + tiles 0 and 1 (32KB each = 8 cp16/thread) ----
    cp16(smb + OFF_WN + tid * 16, g_wn + tid * 4);
#pragma unroll
    for (int i = 0; i < 8; i++) {
        int off = (tid + i * BLOCK) * 16;
        cp16(smb + OFF_W + off, g_wsw[0][0] + off);
    }
    asm volatile("cp.async.commit_group;" ::: "memory");
#pragma unroll
    for (int i = 0; i < 8; i++) {
        int off = (tid + i * BLOCK) * 16;
        cp16(smb + OFF_W + W_BUF + off, g_wsw[1][0] + off);
    }
    asm volatile("cp.async.commit_group;" ::: "memory");

    // ---- build Y = -2x (fp16 hi/lo, swizzled) + partial ||x||^2 ----
    {
        const int p  = tid & 127;
        const int d0 = (tid >> 7) * 32;
        const float* xp = x + (size_t)bimg * D * HW + hw0 + p;
        char* yhi = sm + OFF_YHI;
        char* ylo = sm + OFF_YLO;
        const uint32_t rb = (uint32_t)p * 128;
        float xs = 0.0f;
#pragma unroll
        for (int dd = 0; dd < 32; dd += 2) {
            const int d = d0 + dd;
            float xv0 = xp[(size_t)d * HW];
            float xv1 = xp[(size_t)(d + 1) * HW];
            xs = fmaf(xv0, xv0, xs);
            xs = fmaf(xv1, xv1, xs);
            float v0 = -2.0f * xv0, v1 = -2.0f * xv1;
            __half h0 = __float2half_rn(v0), h1 = __float2half_rn(v1);
            __half l0 = __float2half_rn(v0 - __half2float(h0));
            __half l1 = __float2half_rn(v1 - __half2float(h1));
            uint32_t o = SW(rb + (uint32_t)d * 2);
            *(__half2*)(yhi + o) = __halves2half2(h0, h1);
            *(__half2*)(ylo + o) = __halves2half2(l0, l1);
        }
        ((float*)(sm + OFF_XN))[(tid >> 7) * 128 + p] = xs;
    }
    __syncthreads();   // Y + xn partials visible

    // ---- per-lane row norms: xn + 1 (scores become ||x-w||^2 + 1 >= ~1) ----
    float xnA, xnB;
    {
        const float* xpart = (const float*)(sm + OFF_XN);
        const int r0 = warp * 16 + (lane >> 2);
        xnA = xpart[r0] + xpart[128 + r0] + 1.0f;
        xnB = xpart[r0 + 8] + xpart[128 + r0 + 8] + 1.0f;
    }

    // ---- A fragments (this warp's 16 points x 64 d), hi and lo, in regs ----
    uint32_t ahi[4][4], alo[4][4];
    const int lr = lane & 7;
    const int mI = lane >> 3;
    {
        const uint32_t arow = (uint32_t)(warp * 16 + (mI & 1) * 8 + lr) * 128;
#pragma unroll
        for (int kc = 0; kc < 4; kc++) {
            uint32_t ch = (uint32_t)((kc * 2 + (mI >> 1)) ^ lr) * 16;
            ldsm4(ahi[kc], smb + OFF_YHI + arow + ch);
            ldsm4(alo[kc], smb + OFF_YLO + arow + ch);
        }
    }

    const uint32_t offb0 = (uint32_t)lr * 128 + (uint32_t)(mI ^ lr) * 16;       // k-chunks 0-3
    const uint32_t offb1 = (uint32_t)lr * 128 + (uint32_t)((4 + mI) ^ lr) * 16; // k-chunks 4-7
    const float* wn = (const float*)(sm + OFF_WN);

    uint32_t kA1 = 0xFFFFFFFFu, kA2 = 0xFFFFFFFFu;
    uint32_t kB1 = 0xFFFFFFFFu, kB2 = 0xFFFFFFFFu;

#pragma unroll 1
    for (int kt = 0; kt < KT; kt++) {
        const int buf = kt & 1;
        if (kt < KT - 1) asm volatile("cp.async.wait_group 1;" ::: "memory");
        else             asm volatile("cp.async.wait_group 0;" ::: "memory");
        __syncthreads();   // tile visible; prior compute on buf done

        const uint32_t gbhi = smb + OFF_W + (uint32_t)buf * W_BUF;
        const uint32_t gblo = gbhi + 16384;

#pragma unroll 1
        for (int g = 0; g < WTILE / 32; g++) {
            const uint32_t th = gbhi + (uint32_t)g * 32 * 128;
            const uint32_t tl = gblo + (uint32_t)g * 32 * 128;
            const int colb = kt * WTILE + g * 32 + 2 * (lane & 3);

            float c[4][4];
#pragma unroll
            for (int nt = 0; nt < 4; nt++) {
                float2 nn = *(const float2*)(wn + colb + nt * 8);
                c[nt][0] = nn.x + xnA; c[nt][1] = nn.y + xnA;
                c[nt][2] = nn.x + xnB; c[nt][3] = nn.y + xnB;
            }

            // pass group 1: B = hi, A in {hi, lo}
#pragma unroll
            for (int kc32 = 0; kc32 < 2; kc32++) {
                const uint32_t ob = kc32 ? offb1 : offb0;
#pragma unroll
                for (int nt = 0; nt < 4; nt++) {
                    uint32_t bb[4];
                    ldsm4(bb, th + (uint32_t)nt * 1024 + ob);
                    mma16816(c[nt], ahi[kc32 * 2],     bb[0], bb[1]);
                    mma16816(c[nt], ahi[kc32 * 2 + 1], bb[2], bb[3]);
                    mma16816(c[nt], alo[kc32 * 2],     bb[0], bb[1]);
                    mma16816(c[nt], alo[kc32 * 2 + 1], bb[2], bb[3]);
                }
            }
            // pass group 2: B = lo, A = hi
#pragma unroll
            for (int kc32 = 0; kc32 < 2; kc32++) {
                const uint32_t ob = kc32 ? offb1 : offb0;
#pragma unroll
                for (int nt = 0; nt < 4; nt++) {
                    uint32_t bb[4];
                    ldsm4(bb, tl + (uint32_t)nt * 1024 + ob);
                    mma16816(c[nt], ahi[kc32 * 2],     bb[0], bb[1]);
                    mma16816(c[nt], ahi[kc32 * 2 + 1], bb[2], bb[3]);
                }
            }

            // ---- parallel tournament top-2 epilogue ----
            {
                uint32_t kA[8], kB[8];
#pragma unroll
                for (int nt = 0; nt < 4; nt++) {
                    const int c0 = colb + nt * 8;
                    kA[2*nt]   = fkey(c[nt][0], c0);
                    kA[2*nt+1] = fkey(c[nt][1], c0 + 1);
                    kB[2*nt]   = fkey(c[nt][2], c0);
                    kB[2*nt+1] = fkey(c[nt][3], c0 + 1);
                }
                uint32_t t1, t2;
                top2of8(kA, t1, t2);
                {
                    uint32_t n1 = umn(kA1, t1);
                    uint32_t n2 = umn(umx(kA1, t1), umn(kA2, t2));
                    kA1 = n1; kA2 = n2;
                }
                top2of8(kB, t1, t2);
                {
                    uint32_t n1 = umn(kB1, t1);
                    uint32_t n2 = umn(umx(kB1, t1), umn(kB2, t2));
                    kB1 = n1; kB2 = n2;
                }
            }
        }
        __syncthreads();   // compute on buf done -> safe to overwrite
        if (kt + 2 < KT) {
            uint32_t dst = smb + OFF_W + (uint32_t)buf * W_BUF;
            const char* src = g_wsw[kt + 2][0];
#pragma unroll
            for (int i = 0; i < 8; i++) {
                int off = (tid + i * BLOCK) * 16;
                cp16(dst + off, src + off);
            }
            asm volatile("cp.async.commit_group;" ::: "memory");
        }
    }

    // ---- merge top-2 across the 4 lanes sharing each row ----
#pragma unroll
    for (int mm = 1; mm <= 2; mm <<= 1) {
        uint32_t o1, o2, mn;
        o1 = __shfl_xor_sync(0xFFFFFFFFu, kA1, mm);
        o2 = __shfl_xor_sync(0xFFFFFFFFu, kA2, mm);
        mn = umn(kA1, o1); kA2 = umn(umn(kA2, o2), umx(kA1, o1)); kA1 = mn;
        o1 = __shfl_xor_sync(0xFFFFFFFFu, kB1, mm);
        o2 = __shfl_xor_sync(0xFFFFFFFFu, kB2, mm);
        mn = umn(kB1, o1); kB2 = umn(umn(kB2, o2), umx(kB1, o1)); kB1 = mn;
    }
    if ((lane & 3) == 0) {
        uint2* top = (uint2*)(sm + OFF_TOP);
        const int pA = warp * 16 + (lane >> 2);
        top[pA]     = make_uint2(kA1, kA2);
        top[pA + 8] = make_uint2(kB1, kB2);
    }
    __syncthreads();

    // ---- exact fp32 rerank of the two candidates (always) ----
    int* sidx = (int*)(sm + OFF_IDX);
    if (tid < MTILE) {
        uint2 t = ((const uint2*)(sm + OFF_TOP))[tid];
        int i1 = (int)(t.x & 1023u), i2 = (int)(t.y & 1023u);
        int fi = i1;
        if (i2 != i1) {
            const float* xr = x + (size_t)bimg * D * HW + hw0 + tid;
            const float* w1 = w + (size_t)i1 * D;
            const float* w2 = w + (size_t)i2 * D;
            float s1 = 0.0f, s2 = 0.0f;
#pragma unroll 8
            for (int d = 0; d < D; d++) {
                float xv = xr[(size_t)d * HW];
                float a = w1[d], cc = w2[d];
                s1 = fmaf(a,  fmaf(-2.0f, xv, a),  s1);
                s2 = fmaf(cc, fmaf(-2.0f, xv, cc), s2);
            }
            if (s2 < s1 || (s2 == s1 && i2 < i1)) fi = i2;
        }
        sidx[tid] = fi;
    }
    __syncthreads();

    // ---- coalesced gather of winning codewords ----
    {
        const float4* w4 = (const float4*)w;
        float4* o4 = (float4*)out;
        const size_t obase = (size_t)blockIdx.x * MTILE * (D / 4);
#pragma unroll 4
        for (int i = tid; i < MTILE * (D / 4); i += BLOCK) {
            const int p = i >> 4, d4 = i & 15;
            o4[obase + i] = w4[(size_t)sidx[p] * (D / 4) + d4];
        }
    }
}

extern "C" void kernel_launch(void* const* d_in, const int* in_sizes, int n_in,
                              void* d_out, int out_size)
{
    const float* x = (const float*)d_in[0];   // [64, 64, 32, 32]
    const float* w = (const float*)d_in[1];   // [1024, 64]
    float* out = (float*)d_out;               // [65536, 64]
    (void)in_sizes; (void)n_in; (void)out_size;

    vq_prep_kernel<<<128, 256>>>(w);
    cudaFuncSetAttribute(vq_hmma_kernel, cudaFuncAttributeMaxDynamicSharedMemorySize, SMEM_TOTAL);
    vq_hmma_kernel<<<65536 / MTILE, BLOCK, SMEM_TOTAL>>>(x, w, out);
}

// round 11
// speedup vs baseline: 1.1620x; 1.0361x over previous
#include <cuda_runtime.h>
#include <cuda_fp16.h>
#include <cstdint>

// VectorQuantizer: single-pass fp16 mma.sync screening (m16n8k16, fp32 acc)
// + sorted top-4 candidate tracking + exact fp32 rerank of the 4 candidates.
// score ~= ||w||^2 + ||x||^2 + 1 + (-2x)_fp16 . w_fp16   (>= ~1, u32-ordered)

#define D      64
#define K      1024
#define MTILE  128        // points per CTA (8 warps x 16 rows)
#define WTILE  128        // codewords per tile
#define KT     (K / WTILE)
#define BLOCK  256
#define HW     1024       // d-stride inside x

// ---- smem layout (bytes) ----
#define OFF_Y   0                 // 128 x 128B fp16 (hi only)
#define OFF_W   16384             // 2 bufs x 16KB
#define W_BUF   16384
#define OFF_WN  49152             // 1024 fp32 norms
#define OFF_XN  53248             // 2 x 128 fp32 partial ||x||^2
#define OFF_TOP 54272             // 128 x uint4 (sorted top-4 keys)
#define OFF_IDX 56320             // 128 int
#define SMEM_TOTAL 56832

#define SW(o) ((o) ^ (((o) >> 3) & 0x70))

// ---- global scratch: swizzled fp16 codebook tiles + norms ----
__device__ __align__(1024) static char  g_wsw[KT][WTILE * 128];
__device__ __align__(16)   static float g_wn[K];

static __device__ __forceinline__ uint32_t smem_u32(const void* p) {
    uint32_t a;
    asm("{ .reg .u64 t; cvta.to.shared.u64 t, %1; cvt.u32.u64 %0, t; }" : "=r"(a) : "l"(p));
    return a;
}
static __device__ __forceinline__ void cp16(uint32_t saddr, const void* g) {
    asm volatile("cp.async.cg.shared.global [%0], [%1], 16;"
                 :: "r"(saddr), "l"((size_t)__cvta_generic_to_global(g)) : "memory");
}
static __device__ __forceinline__ void ldsm4(uint32_t r[4], uint32_t addr) {
    asm volatile("ldmatrix.sync.aligned.m8n8.x4.shared.b16 {%0,%1,%2,%3}, [%4];"
                 : "=r"(r[0]), "=r"(r[1]), "=r"(r[2]), "=r"(r[3]) : "r"(addr));
}
static __device__ __forceinline__ void mma16816(float c[4], const uint32_t a[4],
                                                uint32_t b0, uint32_t b1) {
    asm volatile("mma.sync.aligned.m16n8k16.row.col.f32.f16.f16.f32 "
                 "{%0,%1,%2,%3}, {%4,%5,%6,%7}, {%8,%9}, {%0,%1,%2,%3};"
                 : "+f"(c[0]), "+f"(c[1]), "+f"(c[2]), "+f"(c[3])
                 : "r"(a[0]), "r"(a[1]), "r"(a[2]), "r"(a[3]), "r"(b0), "r"(b1));
}
static __device__ __forceinline__ uint32_t umn(uint32_t a, uint32_t b) { return a < b ? a : b; }
static __device__ __forceinline__ uint32_t umx(uint32_t a, uint32_t b) { return a > b ? a : b; }

// scores >= ~1 -> raw float bits order as u32. 13 mantissa bits + 10 index bits.
static __device__ __forceinline__ uint32_t fkey(float v, int col) {
    return (__float_as_uint(v) & 0xFFFFFC00u) | (uint32_t)col;
}
static __device__ __forceinline__ void mrg2(uint32_t& o1, uint32_t& o2,
                                            uint32_t a1, uint32_t a2,
                                            uint32_t b1, uint32_t b2) {
    o1 = umn(a1, b1);
    o2 = umn(umx(a1, b1), umn(a2, b2));
}
// sorted top-2 of 8 keys
static __device__ __forceinline__ void top2of8(const uint32_t k[8],
                                               uint32_t& t1, uint32_t& t2) {
    uint32_t a1 = umn(k[0], k[1]), a2 = umx(k[0], k[1]);
    uint32_t b1 = umn(k[2], k[3]), b2 = umx(k[2], k[3]);
    uint32_t c1 = umn(k[4], k[5]), c2 = umx(k[4], k[5]);
    uint32_t d1 = umn(k[6], k[7]), d2 = umx(k[6], k[7]);
    uint32_t e1, e2, f1, f2;
    mrg2(e1, e2, a1, a2, b1, b2);
    mrg2(f1, f2, c1, c2, d1, d2);
    mrg2(t1, t2, e1, e2, f1, f2);
}
// insert sorted pair (t1<=t2) into sorted-4 r[], keep lowest 4 (bitonic merge)
static __device__ __forceinline__ void ins2into4(uint32_t r[4], uint32_t t1, uint32_t t2) {
    uint32_t m0 = r[0];
    uint32_t m1 = r[1];
    uint32_t m2 = umn(r[2], t2);
    uint32_t m3 = umn(r[3], t1);
    uint32_t s0 = umn(m0, m2), s2 = umx(m0, m2);
    uint32_t s1 = umn(m1, m3), s3 = umx(m1, m3);
    r[0] = umn(s0, s1); r[1] = umx(s0, s1);
    r[2] = umn(s2, s3); r[3] = umx(s2, s3);
}
// merge two sorted-4 lists, keep lowest 4 (bitonic merge)
static __device__ __forceinline__ void mrg4(uint32_t r[4], const uint32_t b[4]) {
    uint32_t m0 = umn(r[0], b[3]);
    uint32_t m1 = umn(r[1], b[2]);
    uint32_t m2 = umn(r[2], b[1]);
    uint32_t m3 = umn(r[3], b[0]);
    uint32_t s0 = umn(m0, m2), s2 = umx(m0, m2);
    uint32_t s1 = umn(m1, m3), s3 = umx(m1, m3);
    r[0] = umn(s0, s1); r[1] = umx(s0, s1);
    r[2] = umn(s2, s3); r[3] = umx(s2, s3);
}

// ---------------- pre-kernel: convert codebook once ----------------
__global__ __launch_bounds__(256)
void vq_prep_kernel(const float* __restrict__ w)
{
    const int gid = blockIdx.x * 256 + threadIdx.x;   // 128 blocks -> 32768 threads
    {
        const int i  = gid;                           // pair index
        const int kr = i >> 5;                        // codeword 0..1023
        const int p  = i & 31;                        // pair within row
        float2 v = ((const float2*)w)[i];
        __half h0 = __float2half_rn(v.x), h1 = __float2half_rn(v.y);
        const int kt = kr >> 7, pr = kr & 127;
        uint32_t o = SW((uint32_t)(pr * 128 + p * 4));
        *(__half2*)(g_wsw[kt] + o) = __halves2half2(h0, h1);
    }
    if (gid < K) {
        const float4* wr = (const float4*)(w + (size_t)gid * D);
        float s = 0.0f;
#pragma unroll
        for (int q = 0; q < D / 4; q++) {
            float4 f = wr[q];
            s = fmaf(f.x, f.x, s); s = fmaf(f.y, f.y, s);
            s = fmaf(f.z, f.z, s); s = fmaf(f.w, f.w, s);
        }
        g_wn[gid] = s;
    }
}

// ---------------- main kernel ----------------
__global__ __launch_bounds__(BLOCK, 3)
void vq_hmma_kernel(const float* __restrict__ x,
                    const float* __restrict__ w,
                    float* __restrict__ out)
{
    extern __shared__ char sm[];
    const uint32_t smb = smem_u32(sm);
    const int tid  = threadIdx.x;
    const int lane = tid & 31;
    const int warp = tid >> 5;

    const int n0   = blockIdx.x * MTILE;
    const int bimg = n0 >> 10;
    const int hw0  = n0 & (HW - 1);

    // ---- prefetch: norms (1 cp16/thread) + tiles 0 and 1 (4 cp16/thread) ----
    cp16(smb + OFF_WN + tid * 16, g_wn + tid * 4);
#pragma unroll
    for (int i = 0; i < 4; i++) {
        int off = (tid + i * BLOCK) * 16;
        cp16(smb + OFF_W + off, g_wsw[0] + off);
    }
    asm volatile("cp.async.commit_group;" ::: "memory");
#pragma unroll
    for (int i = 0; i < 4; i++) {
        int off = (tid + i * BLOCK) * 16;
        cp16(smb + OFF_W + W_BUF + off, g_wsw[1] + off);
    }
    asm volatile("cp.async.commit_group;" ::: "memory");

    // ---- build Y = fp16(-2x) swizzled + partial ||x||^2 ----
    {
        const int p  = tid & 127;
        const int d0 = (tid >> 7) * 32;
        const float* xp = x + (size_t)bimg * D * HW + hw0 + p;
        char* y = sm + OFF_Y;
        const uint32_t rb = (uint32_t)p * 128;
        float xs = 0.0f;
#pragma unroll
        for (int dd = 0; dd < 32; dd += 2) {
            const int d = d0 + dd;
            float xv0 = xp[(size_t)d * HW];
            float xv1 = xp[(size_t)(d + 1) * HW];
            xs = fmaf(xv0, xv0, xs);
            xs = fmaf(xv1, xv1, xs);
            __half h0 = __float2half_rn(-2.0f * xv0);
            __half h1 = __float2half_rn(-2.0f * xv1);
            uint32_t o = SW(rb + (uint32_t)d * 2);
            *(__half2*)(y + o) = __halves2half2(h0, h1);
        }
        ((float*)(sm + OFF_XN))[(tid >> 7) * 128 + p] = xs;
    }
    __syncthreads();   // Y + xn partials visible

    // ---- per-lane row norms: xn + 1 ----
    float xnA, xnB;
    {
        const float* xpart = (const float*)(sm + OFF_XN);
        const int r0 = warp * 16 + (lane >> 2);
        xnA = xpart[r0] + xpart[128 + r0] + 1.0f;
        xnB = xpart[r0 + 8] + xpart[128 + r0 + 8] + 1.0f;
    }

    // ---- A fragments (this warp's 16 points x 64 d) in regs ----
    uint32_t ahi[4][4];
    const int lr = lane & 7;
    const int mI = lane >> 3;
    {
        const uint32_t arow = (uint32_t)(warp * 16 + (mI & 1) * 8 + lr) * 128;
#pragma unroll
        for (int kc = 0; kc < 4; kc++) {
            uint32_t ch = (uint32_t)((kc * 2 + (mI >> 1)) ^ lr) * 16;
            ldsm4(ahi[kc], smb + OFF_Y + arow + ch);
        }
    }

    const uint32_t offb0 = (uint32_t)lr * 128 + (uint32_t)(mI ^ lr) * 16;       // k-chunks 0-3
    const uint32_t offb1 = (uint32_t)lr * 128 + (uint32_t)((4 + mI) ^ lr) * 16; // k-chunks 4-7
    const float* wn = (const float*)(sm + OFF_WN);

    uint32_t rA[4] = {0xFFFFFFFFu, 0xFFFFFFFFu, 0xFFFFFFFFu, 0xFFFFFFFFu};
    uint32_t rB[4] = {0xFFFFFFFFu, 0xFFFFFFFFu, 0xFFFFFFFFu, 0xFFFFFFFFu};

#pragma unroll 1
    for (int kt = 0; kt < KT; kt++) {
        const int buf = kt & 1;
        if (kt < KT - 1) asm volatile("cp.async.wait_group 1;" ::: "memory");
        else             asm volatile("cp.async.wait_group 0;" ::: "memory");
        __syncthreads();   // tile visible; prior compute on buf done

        const uint32_t gb = smb + OFF_W + (uint32_t)buf * W_BUF;

#pragma unroll 1
        for (int g = 0; g < WTILE / 32; g++) {
            const uint32_t th = gb + (uint32_t)g * 32 * 128;
            const int colb = kt * WTILE + g * 32 + 2 * (lane & 3);

            float c[4][4];
#pragma unroll
            for (int nt = 0; nt < 4; nt++) {
                float2 nn = *(const float2*)(wn + colb + nt * 8);
                c[nt][0] = nn.x + xnA; c[nt][1] = nn.y + xnA;
                c[nt][2] = nn.x + xnB; c[nt][3] = nn.y + xnB;
            }

            // single fp16 pass: B = hi, A = hi
#pragma unroll
            for (int kc32 = 0; kc32 < 2; kc32++) {
                const uint32_t ob = kc32 ? offb1 : offb0;
#pragma unroll
                for (int nt = 0; nt < 4; nt++) {
                    uint32_t bb[4];
                    ldsm4(bb, th + (uint32_t)nt * 1024 + ob);
                    mma16816(c[nt], ahi[kc32 * 2],     bb[0], bb[1]);
                    mma16816(c[nt], ahi[kc32 * 2 + 1], bb[2], bb[3]);
                }
            }

            // ---- top-2-of-group -> sorted top-4 running merge ----
            {
                uint32_t kA[8], kB[8];
#pragma unroll
                for (int nt = 0; nt < 4; nt++) {
                    const int c0 = colb + nt * 8;
                    kA[2*nt]   = fkey(c[nt][0], c0);
                    kA[2*nt+1] = fkey(c[nt][1], c0 + 1);
                    kB[2*nt]   = fkey(c[nt][2], c0);
                    kB[2*nt+1] = fkey(c[nt][3], c0 + 1);
                }
                uint32_t t1, t2;
                top2of8(kA, t1, t2);
                ins2into4(rA, t1, t2);
                top2of8(kB, t1, t2);
                ins2into4(rB, t1, t2);
            }
        }
        __syncthreads();   // compute on buf done -> safe to overwrite
        if (kt + 2 < KT) {
            uint32_t dst = smb + OFF_W + (uint32_t)buf * W_BUF;
            const char* src = g_wsw[kt + 2];
#pragma unroll
            for (int i = 0; i < 4; i++) {
                int off = (tid + i * BLOCK) * 16;
                cp16(dst + off, src + off);
            }
            asm volatile("cp.async.commit_group;" ::: "memory");
        }
    }

    // ---- merge sorted top-4 across the 4 lanes sharing each row ----
#pragma unroll
    for (int mm = 1; mm <= 2; mm <<= 1) {
        uint32_t oA[4], oB[4];
#pragma unroll
        for (int q = 0; q < 4; q++) {
            oA[q] = __shfl_xor_sync(0xFFFFFFFFu, rA[q], mm);
            oB[q] = __shfl_xor_sync(0xFFFFFFFFu, rB[q], mm);
        }
        mrg4(rA, oA);
        mrg4(rB, oB);
    }
    if ((lane & 3) == 0) {
        uint4* top = (uint4*)(sm + OFF_TOP);
        const int pA = warp * 16 + (lane >> 2);
        top[pA]     = make_uint4(rA[0], rA[1], rA[2], rA[3]);
        top[pA + 8] = make_uint4(rB[0], rB[1], rB[2], rB[3]);
    }
    __syncthreads();

    // ---- exact fp32 rerank of the 4 candidates ----
    int* sidx = (int*)(sm + OFF_IDX);
    if (tid < MTILE) {
        uint4 t = ((const uint4*)(sm + OFF_TOP))[tid];
        int id[4] = { (int)(t.x & 1023u), (int)(t.y & 1023u),
                      (int)(t.z & 1023u), (int)(t.w & 1023u) };
        const float* xr = x + (size_t)bimg * D * HW + hw0 + tid;
        float xv[D];
#pragma unroll 8
        for (int d = 0; d < D; d++) xv[d] = xr[(size_t)d * HW];
        float bs = 3.402823466e38f;
        int   fi = 0;
#pragma unroll
        for (int j = 0; j < 4; j++) {
            const float* wr = w + (size_t)id[j] * D;
            float s = 0.0f;
#pragma unroll 8
            for (int d = 0; d < D; d++) {
                float a = wr[d];
                s = fmaf(a, fmaf(-2.0f, xv[d], a), s);
            }
            if (s < bs || (s == bs && id[j] < fi)) { bs = s; fi = id[j]; }
        }
        sidx[tid] = fi;
    }
    __syncthreads();

    // ---- coalesced gather of winning codewords ----
    {
        const float4* w4 = (const float4*)w;
        float4* o4 = (float4*)out;
        const size_t obase = (size_t)blockIdx.x * MTILE * (D / 4);
#pragma unroll 4
        for (int i = tid; i < MTILE * (D / 4); i += BLOCK) {
            const int p = i >> 4, d4 = i & 15;
            o4[obase + i] = w4[(size_t)sidx[p] * (D / 4) + d4];
        }
    }
}

extern "C" void kernel_launch(void* const* d_in, const int* in_sizes, int n_in,
                              void* d_out, int out_size)
{
    const float* x = (const float*)d_in[0];   // [64, 64, 32, 32]
    const float* w = (const float*)d_in[1];   // [1024, 64]
    float* out = (float*)d_out;               // [65536, 64]
    (void)in_sizes; (void)n_in; (void)out_size;

    vq_prep_kernel<<<128, 256>>>(w);
    cudaFuncSetAttribute(vq_hmma_kernel, cudaFuncAttributeMaxDynamicSharedMemorySize, SMEM_TOTAL);
    vq_hmma_kernel<<<65536 / MTILE, BLOCK, SMEM_TOTAL>>>(x, w, out);
}

// round 12
// speedup vs baseline: 1.8885x; 1.6251x over previous
#include <cuda_runtime.h>
#include <cuda_fp16.h>
#include <cstdint>

// VectorQuantizer: single-pass fp16 mma.sync screening (m16n8k16, fp32 acc)
// + sorted top-4 candidates + exact fp32 rerank (vectorized float4 loads,
// 2 candidates/thread across all 256 threads, smem reduction).

#define D      64
#define K      1024
#define MTILE  128        // points per CTA (8 warps x 16 rows)
#define WTILE  128        // codewords per tile
#define KT     (K / WTILE)
#define BLOCK  256
#define HW     1024       // d-stride inside x

// ---- smem layout (bytes) ----
#define OFF_Y   0                 // 128 x 128B fp16
#define OFF_W   16384             // 2 bufs x 16KB
#define W_BUF   16384
#define OFF_WN  49152             // 1024 fp32 norms
#define OFF_XN  53248             // 2 x 128 fp32 partial ||x||^2
#define OFF_TOP 54272             // 128 x uint4 (sorted top-4 keys)
#define OFF_RED 56320             // 2 x 128 x uint2 (score, idx)
#define OFF_IDX 58368             // 128 int
#define SMEM_TOTAL 58880

#define SW(o) ((o) ^ (((o) >> 3) & 0x70))

// ---- global scratch: swizzled fp16 codebook tiles + norms ----
__device__ __align__(1024) static char  g_wsw[KT][WTILE * 128];
__device__ __align__(16)   static float g_wn[K];

static __device__ __forceinline__ uint32_t smem_u32(const void* p) {
    uint32_t a;
    asm("{ .reg .u64 t; cvta.to.shared.u64 t, %1; cvt.u32.u64 %0, t; }" : "=r"(a) : "l"(p));
    return a;
}
static __device__ __forceinline__ void cp16(uint32_t saddr, const void* g) {
    asm volatile("cp.async.cg.shared.global [%0], [%1], 16;"
                 :: "r"(saddr), "l"((size_t)__cvta_generic_to_global(g)) : "memory");
}
static __device__ __forceinline__ void ldsm4(uint32_t r[4], uint32_t addr) {
    asm volatile("ldmatrix.sync.aligned.m8n8.x4.shared.b16 {%0,%1,%2,%3}, [%4];"
                 : "=r"(r[0]), "=r"(r[1]), "=r"(r[2]), "=r"(r[3]) : "r"(addr));
}
static __device__ __forceinline__ void mma16816(float c[4], const uint32_t a[4],
                                                uint32_t b0, uint32_t b1) {
    asm volatile("mma.sync.aligned.m16n8k16.row.col.f32.f16.f16.f32 "
                 "{%0,%1,%2,%3}, {%4,%5,%6,%7}, {%8,%9}, {%0,%1,%2,%3};"
                 : "+f"(c[0]), "+f"(c[1]), "+f"(c[2]), "+f"(c[3])
                 : "r"(a[0]), "r"(a[1]), "r"(a[2]), "r"(a[3]), "r"(b0), "r"(b1));
}
static __device__ __forceinline__ uint32_t umn(uint32_t a, uint32_t b) { return a < b ? a : b; }
static __device__ __forceinline__ uint32_t umx(uint32_t a, uint32_t b) { return a > b ? a : b; }

// scores >= ~1 -> raw float bits order as u32. 13 mantissa bits + 10 index bits.
static __device__ __forceinline__ uint32_t fkey(float v, int col) {
    return (__float_as_uint(v) & 0xFFFFFC00u) | (uint32_t)col;
}
static __device__ __forceinline__ void mrg2(uint32_t& o1, uint32_t& o2,
                                            uint32_t a1, uint32_t a2,
                                            uint32_t b1, uint32_t b2) {
    o1 = umn(a1, b1);
    o2 = umn(umx(a1, b1), umn(a2, b2));
}
// sorted top-2 of 8 keys
static __device__ __forceinline__ void top2of8(const uint32_t k[8],
                                               uint32_t& t1, uint32_t& t2) {
    uint32_t a1 = umn(k[0], k[1]), a2 = umx(k[0], k[1]);
    uint32_t b1 = umn(k[2], k[3]), b2 = umx(k[2], k[3]);
    uint32_t c1 = umn(k[4], k[5]), c2 = umx(k[4], k[5]);
    uint32_t d1 = umn(k[6], k[7]), d2 = umx(k[6], k[7]);
    uint32_t e1, e2, f1, f2;
    mrg2(e1, e2, a1, a2, b1, b2);
    mrg2(f1, f2, c1, c2, d1, d2);
    mrg2(t1, t2, e1, e2, f1, f2);
}
// insert sorted pair (t1<=t2) into sorted-4 r[], keep lowest 4
static __device__ __forceinline__ void ins2into4(uint32_t r[4], uint32_t t1, uint32_t t2) {
    uint32_t m0 = r[0];
    uint32_t m1 = r[1];
    uint32_t m2 = umn(r[2], t2);
    uint32_t m3 = umn(r[3], t1);
    uint32_t s0 = umn(m0, m2), s2 = umx(m0, m2);
    uint32_t s1 = umn(m1, m3), s3 = umx(m1, m3);
    r[0] = umn(s0, s1); r[1] = umx(s0, s1);
    r[2] = umn(s2, s3); r[3] = umx(s2, s3);
}
// merge two sorted-4 lists, keep lowest 4
static __device__ __forceinline__ void mrg4(uint32_t r[4], const uint32_t b[4]) {
    uint32_t m0 = umn(r[0], b[3]);
    uint32_t m1 = umn(r[1], b[2]);
    uint32_t m2 = umn(r[2], b[1]);
    uint32_t m3 = umn(r[3], b[0]);
    uint32_t s0 = umn(m0, m2), s2 = umx(m0, m2);
    uint32_t s1 = umn(m1, m3), s3 = umx(m1, m3);
    r[0] = umn(s0, s1); r[1] = umx(s0, s1);
    r[2] = umn(s2, s3); r[3] = umx(s2, s3);
}

// ---------------- pre-kernel: convert codebook once ----------------
__global__ __launch_bounds__(256)
void vq_prep_kernel(const float* __restrict__ w)
{
    const int gid = blockIdx.x * 256 + threadIdx.x;   // 128 blocks -> 32768 threads
    {
        const int i  = gid;                           // pair index
        const int kr = i >> 5;                        // codeword 0..1023
        const int p  = i & 31;                        // pair within row
        float2 v = ((const float2*)w)[i];
        __half h0 = __float2half_rn(v.x), h1 = __float2half_rn(v.y);
        const int kt = kr >> 7, pr = kr & 127;
        uint32_t o = SW((uint32_t)(pr * 128 + p * 4));
        *(__half2*)(g_wsw[kt] + o) = __halves2half2(h0, h1);
    }
    if (gid < K) {
        const float4* wr = (const float4*)(w + (size_t)gid * D);
        float s = 0.0f;
#pragma unroll
        for (int q = 0; q < D / 4; q++) {
            float4 f = wr[q];
            s = fmaf(f.x, f.x, s); s = fmaf(f.y, f.y, s);
            s = fmaf(f.z, f.z, s); s = fmaf(f.w, f.w, s);
        }
        g_wn[gid] = s;
    }
}

// ---------------- main kernel ----------------
__global__ __launch_bounds__(BLOCK, 3)
void vq_hmma_kernel(const float* __restrict__ x,
                    const float* __restrict__ w,
                    float* __restrict__ out)
{
    extern __shared__ char sm[];
    const uint32_t smb = smem_u32(sm);
    const int tid  = threadIdx.x;
    const int lane = tid & 31;
    const int warp = tid >> 5;

    const int n0   = blockIdx.x * MTILE;
    const int bimg = n0 >> 10;
    const int hw0  = n0 & (HW - 1);

    // ---- prefetch: norms + tiles 0 and 1 ----
    cp16(smb + OFF_WN + tid * 16, g_wn + tid * 4);
#pragma unroll
    for (int i = 0; i < 4; i++) {
        int off = (tid + i * BLOCK) * 16;
        cp16(smb + OFF_W + off, g_wsw[0] + off);
    }
    asm volatile("cp.async.commit_group;" ::: "memory");
#pragma unroll
    for (int i = 0; i < 4; i++) {
        int off = (tid + i * BLOCK) * 16;
        cp16(smb + OFF_W + W_BUF + off, g_wsw[1] + off);
    }
    asm volatile("cp.async.commit_group;" ::: "memory");

    // ---- build Y = fp16(-2x) swizzled + partial ||x||^2 ----
    {
        const int p  = tid & 127;
        const int d0 = (tid >> 7) * 32;
        const float* xp = x + (size_t)bimg * D * HW + hw0 + p;
        char* y = sm + OFF_Y;
        const uint32_t rb = (uint32_t)p * 128;
        float xs = 0.0f;
#pragma unroll
        for (int dd = 0; dd < 32; dd += 2) {
            const int d = d0 + dd;
            float xv0 = xp[(size_t)d * HW];
            float xv1 = xp[(size_t)(d + 1) * HW];
            xs = fmaf(xv0, xv0, xs);
            xs = fmaf(xv1, xv1, xs);
            __half h0 = __float2half_rn(-2.0f * xv0);
            __half h1 = __float2half_rn(-2.0f * xv1);
            uint32_t o = SW(rb + (uint32_t)d * 2);
            *(__half2*)(y + o) = __halves2half2(h0, h1);
        }
        ((float*)(sm + OFF_XN))[(tid >> 7) * 128 + p] = xs;
    }
    __syncthreads();   // Y + xn partials visible

    // ---- per-lane row norms: xn + 1 ----
    float xnA, xnB;
    {
        const float* xpart = (const float*)(sm + OFF_XN);
        const int r0 = warp * 16 + (lane >> 2);
        xnA = xpart[r0] + xpart[128 + r0] + 1.0f;
        xnB = xpart[r0 + 8] + xpart[128 + r0 + 8] + 1.0f;
    }

    // ---- A fragments (this warp's 16 points x 64 d) in regs ----
    uint32_t ahi[4][4];
    const int lr = lane & 7;
    const int mI = lane >> 3;
    {
        const uint32_t arow = (uint32_t)(warp * 16 + (mI & 1) * 8 + lr) * 128;
#pragma unroll
        for (int kc = 0; kc < 4; kc++) {
            uint32_t ch = (uint32_t)((kc * 2 + (mI >> 1)) ^ lr) * 16;
            ldsm4(ahi[kc], smb + OFF_Y + arow + ch);
        }
    }

    const uint32_t offb0 = (uint32_t)lr * 128 + (uint32_t)(mI ^ lr) * 16;       // k-chunks 0-3
    const uint32_t offb1 = (uint32_t)lr * 128 + (uint32_t)((4 + mI) ^ lr) * 16; // k-chunks 4-7
    const float* wn = (const float*)(sm + OFF_WN);

    uint32_t rA[4] = {0xFFFFFFFFu, 0xFFFFFFFFu, 0xFFFFFFFFu, 0xFFFFFFFFu};
    uint32_t rB[4] = {0xFFFFFFFFu, 0xFFFFFFFFu, 0xFFFFFFFFu, 0xFFFFFFFFu};

#pragma unroll 1
    for (int kt = 0; kt < KT; kt++) {
        const int buf = kt & 1;
        if (kt < KT - 1) asm volatile("cp.async.wait_group 1;" ::: "memory");
        else             asm volatile("cp.async.wait_group 0;" ::: "memory");
        __syncthreads();   // tile visible; prior compute on buf done

        const uint32_t gb = smb + OFF_W + (uint32_t)buf * W_BUF;

#pragma unroll 1
        for (int g = 0; g < WTILE / 32; g++) {
            const uint32_t th = gb + (uint32_t)g * 32 * 128;
            const int colb = kt * WTILE + g * 32 + 2 * (lane & 3);

            float c[4][4];
#pragma unroll
            for (int nt = 0; nt < 4; nt++) {
                float2 nn = *(const float2*)(wn + colb + nt * 8);
                c[nt][0] = nn.x + xnA; c[nt][1] = nn.y + xnA;
                c[nt][2] = nn.x + xnB; c[nt][3] = nn.y + xnB;
            }

            // single fp16 pass
#pragma unroll
            for (int kc32 = 0; kc32 < 2; kc32++) {
                const uint32_t ob = kc32 ? offb1 : offb0;
#pragma unroll
                for (int nt = 0; nt < 4; nt++) {
                    uint32_t bb[4];
                    ldsm4(bb, th + (uint32_t)nt * 1024 + ob);
                    mma16816(c[nt], ahi[kc32 * 2],     bb[0], bb[1]);
                    mma16816(c[nt], ahi[kc32 * 2 + 1], bb[2], bb[3]);
                }
            }

            // ---- top-2-of-group -> sorted top-4 running merge ----
            {
                uint32_t kA[8], kB[8];
#pragma unroll
                for (int nt = 0; nt < 4; nt++) {
                    const int c0 = colb + nt * 8;
                    kA[2*nt]   = fkey(c[nt][0], c0);
                    kA[2*nt+1] = fkey(c[nt][1], c0 + 1);
                    kB[2*nt]   = fkey(c[nt][2], c0);
                    kB[2*nt+1] = fkey(c[nt][3], c0 + 1);
                }
                uint32_t t1, t2;
                top2of8(kA, t1, t2);
                ins2into4(rA, t1, t2);
                top2of8(kB, t1, t2);
                ins2into4(rB, t1, t2);
            }
        }
        __syncthreads();   // compute on buf done -> safe to overwrite
        if (kt + 2 < KT) {
            uint32_t dst = smb + OFF_W + (uint32_t)buf * W_BUF;
            const char* src = g_wsw[kt + 2];
#pragma unroll
            for (int i = 0; i < 4; i++) {
                int off = (tid + i * BLOCK) * 16;
                cp16(dst + off, src + off);
            }
            asm volatile("cp.async.commit_group;" ::: "memory");
        }
    }

    // ---- merge sorted top-4 across the 4 lanes sharing each row ----
#pragma unroll
    for (int mm = 1; mm <= 2; mm <<= 1) {
        uint32_t oA[4], oB[4];
#pragma unroll
        for (int q = 0; q < 4; q++) {
            oA[q] = __shfl_xor_sync(0xFFFFFFFFu, rA[q], mm);
            oB[q] = __shfl_xor_sync(0xFFFFFFFFu, rB[q], mm);
        }
        mrg4(rA, oA);
        mrg4(rB, oB);
    }
    if ((lane & 3) == 0) {
        uint4* top = (uint4*)(sm + OFF_TOP);
        const int pA = warp * 16 + (lane >> 2);
        top[pA]     = make_uint4(rA[0], rA[1], rA[2], rA[3]);
        top[pA + 8] = make_uint4(rB[0], rB[1], rB[2], rB[3]);
    }
    __syncthreads();

    // ---- exact fp32 rerank: 2 candidates/thread, 256 threads, float4 loads ----
    {
        const int p    = tid & 127;
        const int half = tid >> 7;            // 0: cands {0,1}; 1: cands {2,3}
        uint4 t = ((const uint4*)(sm + OFF_TOP))[p];
        int ia = half ? (int)(t.z & 1023u) : (int)(t.x & 1023u);
        int ib = half ? (int)(t.w & 1023u) : (int)(t.y & 1023u);

        const float*  xr  = x + (size_t)bimg * D * HW + hw0 + p;
        const float4* wa4 = (const float4*)(w + (size_t)ia * D);
        const float4* wb4 = (const float4*)(w + (size_t)ib * D);
        float sa = 0.0f, sb = 0.0f;
#pragma unroll
        for (int q = 0; q < D / 4; q++) {
            float4 a = wa4[q];
            float4 b = wb4[q];
            float x0 = xr[(size_t)(4*q + 0) * HW];
            float x1 = xr[(size_t)(4*q + 1) * HW];
            float x2 = xr[(size_t)(4*q + 2) * HW];
            float x3 = xr[(size_t)(4*q + 3) * HW];
            sa = fmaf(a.x, fmaf(-2.0f, x0, a.x), sa);
            sb = fmaf(b.x, fmaf(-2.0f, x0, b.x), sb);
            sa = fmaf(a.y, fmaf(-2.0f, x1, a.y), sa);
            sb = fmaf(b.y, fmaf(-2.0f, x1, b.y), sb);
            sa = fmaf(a.z, fmaf(-2.0f, x2, a.z), sa);
            sb = fmaf(b.z, fmaf(-2.0f, x2, b.z), sb);
            sa = fmaf(a.w, fmaf(-2.0f, x3, a.w), sa);
            sb = fmaf(b.w, fmaf(-2.0f, x3, b.w), sb);
        }
        // best of this thread's two candidates (smallest score, then index)
        float bs = sa; int bi = ia;
        if (sb < bs || (sb == bs && ib < bi)) { bs = sb; bi = ib; }
        uint2* red = (uint2*)(sm + OFF_RED);
        red[half * 128 + p] = make_uint2(__float_as_uint(bs), (uint32_t)bi);
    }
    __syncthreads();

    int* sidx = (int*)(sm + OFF_IDX);
    if (tid < MTILE) {
        const uint2* red = (const uint2*)(sm + OFF_RED);
        uint2 r0 = red[tid];
        uint2 r1 = red[128 + tid];
        float s0 = __uint_as_float(r0.x), s1 = __uint_as_float(r1.x);
        int   i0 = (int)r0.y,             i1 = (int)r1.y;
        int fi = i0;
        if (s1 < s0 || (s1 == s0 && i1 < i0)) fi = i1;
        sidx[tid] = fi;
    }
    __syncthreads();

    // ---- coalesced gather of winning codewords ----
    {
        const float4* w4 = (const float4*)w;
        float4* o4 = (float4*)out;
        const size_t obase = (size_t)blockIdx.x * MTILE * (D / 4);
#pragma unroll 4
        for (int i = tid; i < MTILE * (D / 4); i += BLOCK) {
            const int p = i >> 4, d4 = i & 15;
            o4[obase + i] = w4[(size_t)sidx[p] * (D / 4) + d4];
        }
    }
}

extern "C" void kernel_launch(void* const* d_in, const int* in_sizes, int n_in,
                              void* d_out, int out_size)
{
    const float* x = (const float*)d_in[0];   // [64, 64, 32, 32]
    const float* w = (const float*)d_in[1];   // [1024, 64]
    float* out = (float*)d_out;               // [65536, 64]
    (void)in_sizes; (void)n_in; (void)out_size;

    vq_prep_kernel<<<128, 256>>>(w);
    cudaFuncSetAttribute(vq_hmma_kernel, cudaFuncAttributeMaxDynamicSharedMemorySize, SMEM_TOTAL);
    vq_hmma_kernel<<<65536 / MTILE, BLOCK, SMEM_TOTAL>>>(x, w, out);
}